// round 1
// baseline (speedup 1.0000x reference)
#include <cuda_runtime.h>
#include <cuda_bf16.h>

// Problem constants (fixed by reference): 
//   P=Q=3, M=N=127, DIM=3, SU=SV=256, B=16, EPS=1e-8
#define PB    16
#define PDEG  3
#define PM    127          // max span (== M == N)
#define PL    132          // knot vector length  (M + P + 2)
#define PS    256          // samples per direction (SU == SV)
#define PNC   128          // control points per direction (M+1 == N+1)
#define PDIM  3
#define PEPS  1e-8f

// ---- device scratch (allocation-free) ----
__device__ float g_Nu[PB][PDEG + 1][PS];
__device__ float g_Nv[PB][PDEG + 1][PS];
__device__ int   g_uspan[PB][PS];
__device__ int   g_vspan[PB][PS];

// ---------------------------------------------------------------------------
// Kernel 1: knot normalization + span find + Cox-de Boor basis.
// grid.x = 2*B  (blockIdx.x < B -> u direction; else v direction)
// blockDim = PS (256) threads, thread s handles sample s.
// ---------------------------------------------------------------------------
__global__ void surf_basis_kernel(const float* __restrict__ knot_u,
                                  const float* __restrict__ knot_v,
                                  const float* __restrict__ u,
                                  const float* __restrict__ v)
{
    const int bid = blockIdx.x;
    const bool is_u = (bid < PB);
    const int b = is_u ? bid : (bid - PB);
    const float* knots = (is_u ? knot_u : knot_v) + b * PL;
    const float* tarr  = is_u ? u : v;
    float* Nout  = is_u ? &g_Nu[b][0][0] : &g_Nv[b][0][0];
    int*   Sout  = is_u ? &g_uspan[b][0] : &g_vspan[b][0];

    __shared__ float sKc[PL];   // cumsum
    __shared__ float sK[PL];    // normalized knots

    const int tid = threadIdx.x;

    // serial cumsum (132 adds) to match jnp.cumsum float32 sequential order
    if (tid == 0) {
        float acc = 0.0f;
        for (int i = 0; i < PL; i++) {
            float x = knots[i];
            if (x < 0.0f) x = 0.0001f;
            acc += x;
            sKc[i] = acc;
        }
    }
    __syncthreads();

    const float k0 = sKc[0];
    const float inv = 1.0f / (sKc[PL - 1] - k0);
    for (int i = tid; i < PL; i += blockDim.x)
        sK[i] = (sKc[i] - k0) * inv;
    __syncthreads();

    // one thread per sample
    const int s = tid;
    const float t = tarr[s];

    // span: argmin over masked = (d > EPS ? d : 1.0), d = t - K[deg + i],
    // i in [0, PL - 2*deg). First-occurrence-of-min semantics (strict <).
    float best = 1.0f;   // masked values never exceed 1.0; bi=0 default matches argmin
    int   bi = 0;
    const int cnt = PL - 2 * PDEG;   // 126
    for (int i = 0; i < cnt; i++) {
        float d = t - sK[PDEG + i];
        float m = (d > PEPS) ? d : 1.0f;
        if (m < best) { best = m; bi = i; }
    }
    int span = bi + PDEG;
    if (span < PDEG) span = PDEG;
    if (span > PM)   span = PM;
    Sout[s] = span;

    // Cox-de Boor, deg = 3, replicating reference's denom==0 handling
    float Ni[PDEG + 1];
    Ni[0] = 1.0f; Ni[1] = 0.0f; Ni[2] = 0.0f; Ni[3] = 0.0f;
    #pragma unroll
    for (int k = 1; k <= PDEG; k++) {
        float saved = 0.0f;
        #pragma unroll
        for (int r = 0; r < PDEG; r++) {
            if (r >= k) break;
            float K1 = sK[span + r + 1];
            float K2 = sK[span + 1 - k + r];
            float denom = (K1 - t) + (t - K2);
            float temp = (denom == 0.0f) ? 0.0001f : (Ni[r] / denom);
            Ni[r] = saved + (K1 - t) * temp;
            saved = (t - K2) * temp;
        }
        Ni[k] = saved;
    }

    #pragma unroll
    for (int k = 0; k <= PDEG; k++)
        Nout[k * PS + s] = Ni[k];
}

// ---------------------------------------------------------------------------
// Kernel 2: surface evaluation.
// grid.x = B * SU  (one block per (b, u-row)), blockDim = SV (256), thread = v.
// out[b][uu][vv][d] = sum_{p,q} ctrl[b][uspan-3+p][vspan-3+q][d] * Nu[p] * Nv[q]
// ---------------------------------------------------------------------------
__global__ void __launch_bounds__(PS)
surf_eval_kernel(const float* __restrict__ ctrl,
                 float* __restrict__ out)
{
    const int b  = blockIdx.x / PS;
    const int uu = blockIdx.x % PS;
    const int vv = threadIdx.x;

    // u-side data: uniform across the block (broadcast loads)
    const int iu = g_uspan[b][uu] - PDEG;
    float nu[PDEG + 1];
    #pragma unroll
    for (int p = 0; p <= PDEG; p++) nu[p] = g_Nu[b][p][uu];

    // v-side data: per-thread
    const int iv = g_vspan[b][vv] - PDEG;
    float nv[PDEG + 1];
    #pragma unroll
    for (int q = 0; q <= PDEG; q++) nv[q] = g_Nv[b][q][vv];

    const float* base = ctrl + (((long)b * PNC + iu) * PNC + iv) * PDIM;

    float a0 = 0.0f, a1 = 0.0f, a2 = 0.0f;
    #pragma unroll
    for (int p = 0; p <= PDEG; p++) {
        const float* row = base + p * (PNC * PDIM);
        float s0 = 0.0f, s1 = 0.0f, s2 = 0.0f;
        #pragma unroll
        for (int q = 0; q <= PDEG; q++) {
            const float w = nv[q];
            s0 = fmaf(w, __ldg(row + q * PDIM + 0), s0);
            s1 = fmaf(w, __ldg(row + q * PDIM + 1), s1);
            s2 = fmaf(w, __ldg(row + q * PDIM + 2), s2);
        }
        a0 = fmaf(nu[p], s0, a0);
        a1 = fmaf(nu[p], s1, a1);
        a2 = fmaf(nu[p], s2, a2);
    }

    float* o = out + (((long)b * PS + uu) * PS + vv) * PDIM;
    o[0] = a0;
    o[1] = a1;
    o[2] = a2;
}

// ---------------------------------------------------------------------------
extern "C" void kernel_launch(void* const* d_in, const int* in_sizes, int n_in,
                              void* d_out, int out_size)
{
    const float* ctrl   = (const float*)d_in[0];  // (B, 128, 128, 3)
    const float* knot_u = (const float*)d_in[1];  // (B, 132)
    const float* knot_v = (const float*)d_in[2];  // (B, 132)
    const float* u      = (const float*)d_in[3];  // (256,)
    const float* v      = (const float*)d_in[4];  // (256,)
    float* out = (float*)d_out;                   // (B, 256, 256, 3)

    surf_basis_kernel<<<2 * PB, PS>>>(knot_u, knot_v, u, v);
    surf_eval_kernel<<<PB * PS, PS>>>(ctrl, out);
}

// round 2
// speedup vs baseline: 1.4076x; 1.4076x over previous
#include <cuda_runtime.h>
#include <cuda_bf16.h>

// Problem constants (fixed by reference):
//   P=Q=3, M=N=127, DIM=3, SU=SV=256, B=16, EPS=1e-8
#define PB    16
#define PDEG  3
#define PM    127          // max span
#define PL    132          // knot vector length (M + P + 2)
#define PS    256          // samples per direction
#define PNC   128          // control points per direction
#define PDIM  3
#define PEPS  1e-8f
#define TU    4            // u-outputs per thread in eval kernel

// ---- device scratch (allocation-free) ----
__device__ float g_Nu[PB][PDEG + 1][PS];
__device__ float g_Nv[PB][PDEG + 1][PS];
__device__ int   g_uspan[PB][PS];
__device__ int   g_vspan[PB][PS];

// ---------------------------------------------------------------------------
// Kernel 1: knot normalization + span find + Cox-de Boor basis.
// grid.x = 2*B, blockDim = PS.
// ---------------------------------------------------------------------------
__global__ void __launch_bounds__(PS)
surf_basis_kernel(const float* __restrict__ knot_u,
                  const float* __restrict__ knot_v,
                  const float* __restrict__ u,
                  const float* __restrict__ v)
{
    const int bid = blockIdx.x;
    const bool is_u = (bid < PB);
    const int b = is_u ? bid : (bid - PB);
    const float* knots = (is_u ? knot_u : knot_v) + b * PL;
    const float* tarr  = is_u ? u : v;
    float* Nout  = is_u ? &g_Nu[b][0][0] : &g_Nv[b][0][0];
    int*   Sout  = is_u ? &g_uspan[b][0] : &g_vspan[b][0];

    __shared__ float sK[PL];    // scan buffer, then normalized knots
    const int tid = threadIdx.x;

    // inclusive scan of clamped knots (Hillis-Steele, 8 rounds)
    if (tid < PL) {
        float x = knots[tid];
        sK[tid] = (x < 0.0f) ? 0.0001f : x;
    }
    __syncthreads();
    #pragma unroll
    for (int off = 1; off < PL; off <<= 1) {
        float t = 0.0f;
        if (tid < PL && tid >= off) t = sK[tid - off];
        __syncthreads();
        if (tid < PL) sK[tid] += t;
        __syncthreads();
    }

    const float k0  = sK[0];
    const float inv = 1.0f / (sK[PL - 1] - k0);
    __syncthreads();
    if (tid < PL) sK[tid] = (sK[tid] - k0) * inv;
    __syncthreads();

    // one thread per sample
    const int s = tid;
    const float t = tarr[s];

    // span: last i in [0, 126) with t - sK[3+i] > EPS (knots non-decreasing),
    // default 0; tie-walk backwards to match argmin first-occurrence on
    // exactly-equal knot values.
    int j;
    {
        const int cnt = PL - 2 * PDEG;         // 126
        // binary search: first index where NOT (t - sK[3+i] > EPS)
        int lo = 0, hi = cnt;                   // invariant: pred holds < lo
        while (lo < hi) {
            int mid = (lo + hi) >> 1;
            if (t - sK[PDEG + mid] > PEPS) lo = mid + 1;
            else hi = mid;
        }
        j = lo - 1;                             // last index with pred, or -1
        if (j < 0) j = 0;
        else {
            while (j > 0 && sK[PDEG + j - 1] == sK[PDEG + j]) j--;
        }
    }
    int span = j + PDEG;
    if (span < PDEG) span = PDEG;
    if (span > PM)   span = PM;
    Sout[s] = span;

    // Cox-de Boor, deg = 3, replicating reference's denom==0 handling
    float Ni[PDEG + 1];
    Ni[0] = 1.0f; Ni[1] = 0.0f; Ni[2] = 0.0f; Ni[3] = 0.0f;
    #pragma unroll
    for (int k = 1; k <= PDEG; k++) {
        float saved = 0.0f;
        #pragma unroll
        for (int r = 0; r < PDEG; r++) {
            if (r >= k) break;
            float K1 = sK[span + r + 1];
            float K2 = sK[span + 1 - k + r];
            float denom = (K1 - t) + (t - K2);
            float temp = (denom == 0.0f) ? 0.0001f : (Ni[r] / denom);
            Ni[r] = saved + (K1 - t) * temp;
            saved = (t - K2) * temp;
        }
        Ni[k] = saved;
    }

    #pragma unroll
    for (int k = 0; k <= PDEG; k++)
        Nout[k * PS + s] = Ni[k];
}

// ---------------------------------------------------------------------------
// Kernel 2: surface evaluation with u-direction reuse.
// grid.x = B * (SU/TU) = 1024 blocks, blockDim = 256 (thread = vv).
// Each thread computes TU consecutive-u outputs for its (b, vv):
// row-sums over the v-window are computed once per needed ctrl row and
// accumulated into all TU outputs whose u-window covers that row.
// ---------------------------------------------------------------------------
__global__ void __launch_bounds__(PS)
surf_eval_kernel(const float* __restrict__ ctrl,
                 float* __restrict__ out)
{
    const int b   = blockIdx.x / (PS / TU);
    const int ug  = blockIdx.x % (PS / TU);
    const int uu0 = ug * TU;
    const int vv  = threadIdx.x;

    __shared__ float s_nu[TU][PDEG + 1];
    __shared__ int   s_iu[TU];

    const int tid = threadIdx.x;
    if (tid < TU * (PDEG + 1)) {
        int i = tid >> 2, p = tid & 3;
        s_nu[i][p] = g_Nu[b][p][uu0 + i];
    }
    if (tid < TU)
        s_iu[tid] = g_uspan[b][uu0 + tid] - PDEG;
    __syncthreads();

    // per-thread v-side data
    const int iv = g_vspan[b][vv] - PDEG;
    float nv[PDEG + 1];
    #pragma unroll
    for (int q = 0; q <= PDEG; q++) nv[q] = g_Nv[b][q][vv];

    int iu_r[TU];
    #pragma unroll
    for (int i = 0; i < TU; i++) iu_r[i] = s_iu[i];

    int r0 = iu_r[0], r1 = iu_r[0];
    #pragma unroll
    for (int i = 1; i < TU; i++) {
        r0 = min(r0, iu_r[i]);
        r1 = max(r1, iu_r[i]);
    }
    r1 += PDEG;

    float acc[TU][PDIM];
    #pragma unroll
    for (int i = 0; i < TU; i++)
        #pragma unroll
        for (int c = 0; c < PDIM; c++) acc[i][c] = 0.0f;

    const float* cbase = ctrl + ((long)b * PNC * PNC + (long)iv) * PDIM;

    for (int r = r0; r <= r1; ++r) {
        const float* row = cbase + (long)r * (PNC * PDIM);
        float s0 = 0.0f, s1 = 0.0f, s2 = 0.0f;
        #pragma unroll
        for (int q = 0; q <= PDEG; q++) {
            const float w = nv[q];
            s0 = fmaf(w, __ldg(row + q * PDIM + 0), s0);
            s1 = fmaf(w, __ldg(row + q * PDIM + 1), s1);
            s2 = fmaf(w, __ldg(row + q * PDIM + 2), s2);
        }
        #pragma unroll
        for (int i = 0; i < TU; i++) {
            int p = r - iu_r[i];
            if ((unsigned)p <= (unsigned)PDEG) {
                const float w = s_nu[i][p];   // uniform broadcast LDS
                acc[i][0] = fmaf(w, s0, acc[i][0]);
                acc[i][1] = fmaf(w, s1, acc[i][1]);
                acc[i][2] = fmaf(w, s2, acc[i][2]);
            }
        }
    }

    #pragma unroll
    for (int i = 0; i < TU; i++) {
        float* o = out + (((long)b * PS + (uu0 + i)) * PS + vv) * PDIM;
        o[0] = acc[i][0];
        o[1] = acc[i][1];
        o[2] = acc[i][2];
    }
}

// ---------------------------------------------------------------------------
extern "C" void kernel_launch(void* const* d_in, const int* in_sizes, int n_in,
                              void* d_out, int out_size)
{
    const float* ctrl   = (const float*)d_in[0];  // (B, 128, 128, 3)
    const float* knot_u = (const float*)d_in[1];  // (B, 132)
    const float* knot_v = (const float*)d_in[2];  // (B, 132)
    const float* u      = (const float*)d_in[3];  // (256,)
    const float* v      = (const float*)d_in[4];  // (256,)
    float* out = (float*)d_out;                   // (B, 256, 256, 3)

    surf_basis_kernel<<<2 * PB, PS>>>(knot_u, knot_v, u, v);
    surf_eval_kernel<<<PB * (PS / TU), PS>>>(ctrl, out);
}

// round 3
// speedup vs baseline: 1.4320x; 1.0173x over previous
#include <cuda_runtime.h>
#include <cuda_bf16.h>

// Problem constants: P=Q=3, M=N=127, DIM=3, SU=SV=256, B=16
#define PB    16
#define PDEG  3
#define PM    127
#define PL    132          // knot vector length
#define PS    256          // samples per direction
#define PNC   128          // control points per direction
#define PDIM  3
#define PEPS  1e-8f
#define RG    4            // rows per thread in rowsum kernel

// ---- device scratch (allocation-free) ----
__device__ float  g_Nu[PB][PDEG + 1][PS];
__device__ float  g_Nv[PB][PDEG + 1][PS];
__device__ int    g_uspan[PB][PS];
__device__ int    g_vspan[PB][PS];
__device__ float4 g_R[PB][PNC][PS];     // 8 MB rowsum scratch (L2-resident)

// ---------------------------------------------------------------------------
// Kernel 1: knot normalization + span find + Cox-de Boor basis.
// grid.x = 2*B, blockDim = PS. Only 4 barriers (warp-0 shuffle scan).
// ---------------------------------------------------------------------------
__global__ void __launch_bounds__(PS)
surf_basis_kernel(const float* __restrict__ knot_u,
                  const float* __restrict__ knot_v,
                  const float* __restrict__ u,
                  const float* __restrict__ v)
{
    const int bid = blockIdx.x;
    const bool is_u = (bid < PB);
    const int b = is_u ? bid : (bid - PB);
    const float* knots = (is_u ? knot_u : knot_v) + b * PL;
    const float* tarr  = is_u ? u : v;
    float* Nout  = is_u ? &g_Nu[b][0][0] : &g_Nv[b][0][0];
    int*   Sout  = is_u ? &g_uspan[b][0] : &g_vspan[b][0];

    __shared__ float sK[PL];
    const int tid = threadIdx.x;

    if (tid < PL) {
        float x = knots[tid];
        sK[tid] = (x < 0.0f) ? 0.0001f : x;
    }
    __syncthreads();

    // warp 0: inclusive scan of 132 elems via per-lane chunks + shuffle scan
    if (tid < 32) {
        const int CH = 5;                       // 32*5 >= 132
        const int base = tid * CH;
        float vch[CH];
        float run = 0.0f;
        #pragma unroll
        for (int k = 0; k < CH; k++) {
            int i = base + k;
            float x = (i < PL) ? sK[i] : 0.0f;
            run += x;
            vch[k] = run;
        }
        float incl = run;
        #pragma unroll
        for (int off = 1; off < 32; off <<= 1) {
            float nb = __shfl_up_sync(0xffffffffu, incl, off);
            if (tid >= off) incl += nb;
        }
        float excl = incl - run;
        #pragma unroll
        for (int k = 0; k < CH; k++) {
            int i = base + k;
            if (i < PL) sK[i] = excl + vch[k];
        }
    }
    __syncthreads();

    const float k0  = sK[0];
    const float inv = 1.0f / (sK[PL - 1] - k0);
    __syncthreads();
    if (tid < PL) sK[tid] = (sK[tid] - k0) * inv;
    __syncthreads();

    const int s = tid;
    const float t = tarr[s];

    // span: binary search for last i with t - sK[3+i] > EPS, then tie-walk
    int j;
    {
        const int cnt = PL - 2 * PDEG;          // 126
        int lo = 0, hi = cnt;
        while (lo < hi) {
            int mid = (lo + hi) >> 1;
            if (t - sK[PDEG + mid] > PEPS) lo = mid + 1;
            else hi = mid;
        }
        j = lo - 1;
        if (j < 0) j = 0;
        else {
            while (j > 0 && sK[PDEG + j - 1] == sK[PDEG + j]) j--;
        }
    }
    int span = j + PDEG;
    if (span < PDEG) span = PDEG;
    if (span > PM)   span = PM;
    Sout[s] = span;

    // Cox-de Boor, deg = 3, replicating reference's denom==0 handling
    float Ni[PDEG + 1];
    Ni[0] = 1.0f; Ni[1] = 0.0f; Ni[2] = 0.0f; Ni[3] = 0.0f;
    #pragma unroll
    for (int k = 1; k <= PDEG; k++) {
        float saved = 0.0f;
        #pragma unroll
        for (int r = 0; r < PDEG; r++) {
            if (r >= k) break;
            float K1 = sK[span + r + 1];
            float K2 = sK[span + 1 - k + r];
            float denom = (K1 - t) + (t - K2);
            float temp = (denom == 0.0f) ? 0.0001f : (Ni[r] / denom);
            Ni[r] = saved + (K1 - t) * temp;
            saved = (t - K2) * temp;
        }
        Ni[k] = saved;
    }

    #pragma unroll
    for (int k = 0; k <= PDEG; k++)
        Nout[k * PS + s] = Ni[k];
}

// ---------------------------------------------------------------------------
// Kernel 2: rowsums. R[b][r][vv] = sum_q Nv[q][vv] * ctrl[b][r][iv+q][:]
// Each (b,r,vv) computed EXACTLY ONCE. grid = B * (PNC/RG) = 512 blocks.
// ---------------------------------------------------------------------------
__global__ void __launch_bounds__(PS)
surf_rowsum_kernel(const float* __restrict__ ctrl)
{
    const int b     = blockIdx.x / (PNC / RG);
    const int rbase = (blockIdx.x % (PNC / RG)) * RG;
    const int vv    = threadIdx.x;

    const int iv = g_vspan[b][vv] - PDEG;
    float nv[PDEG + 1];
    #pragma unroll
    for (int q = 0; q <= PDEG; q++) nv[q] = g_Nv[b][q][vv];

    const float* base = ctrl + (((long)b * PNC) * PNC + iv) * PDIM;

    #pragma unroll
    for (int j = 0; j < RG; j++) {
        const float* row = base + (long)(rbase + j) * (PNC * PDIM);
        float s0 = 0.0f, s1 = 0.0f, s2 = 0.0f;
        #pragma unroll
        for (int q = 0; q <= PDEG; q++) {
            const float w = nv[q];
            s0 = fmaf(w, __ldg(row + q * PDIM + 0), s0);
            s1 = fmaf(w, __ldg(row + q * PDIM + 1), s1);
            s2 = fmaf(w, __ldg(row + q * PDIM + 2), s2);
        }
        g_R[b][rbase + j][vv] = make_float4(s0, s1, s2, 0.0f);
    }
}

// ---------------------------------------------------------------------------
// Kernel 3: u-contraction. out[b][uu][vv] = sum_p Nu[p][uu] * R[b][iu+p][vv]
// blockDim = (256, 2): 2 u's per block, grid = B * PS/2 = 2048 blocks.
// Loads: 4 coalesced LDG.128 per output.
// ---------------------------------------------------------------------------
__global__ void __launch_bounds__(512)
surf_ucontract_kernel(float* __restrict__ out)
{
    const int b  = blockIdx.x / (PS / 2);
    const int uu = (blockIdx.x % (PS / 2)) * 2 + threadIdx.y;
    const int vv = threadIdx.x;

    const int iu = g_uspan[b][uu] - PDEG;          // uniform per (block,y)
    float nu[PDEG + 1];
    #pragma unroll
    for (int p = 0; p <= PDEG; p++) nu[p] = g_Nu[b][p][uu];

    const float4* Rb = &g_R[b][iu][0];

    float a0 = 0.0f, a1 = 0.0f, a2 = 0.0f;
    #pragma unroll
    for (int p = 0; p <= PDEG; p++) {
        float4 r = __ldg(&Rb[p * PS + vv]);
        const float w = nu[p];
        a0 = fmaf(w, r.x, a0);
        a1 = fmaf(w, r.y, a1);
        a2 = fmaf(w, r.z, a2);
    }

    float* o = out + (((long)b * PS + uu) * PS + vv) * PDIM;
    o[0] = a0;
    o[1] = a1;
    o[2] = a2;
}

// ---------------------------------------------------------------------------
extern "C" void kernel_launch(void* const* d_in, const int* in_sizes, int n_in,
                              void* d_out, int out_size)
{
    const float* ctrl   = (const float*)d_in[0];  // (B, 128, 128, 3)
    const float* knot_u = (const float*)d_in[1];  // (B, 132)
    const float* knot_v = (const float*)d_in[2];  // (B, 132)
    const float* u      = (const float*)d_in[3];  // (256,)
    const float* v      = (const float*)d_in[4];  // (256,)
    float* out = (float*)d_out;                   // (B, 256, 256, 3)

    surf_basis_kernel<<<2 * PB, PS>>>(knot_u, knot_v, u, v);
    surf_rowsum_kernel<<<PB * (PNC / RG), PS>>>(ctrl);
    dim3 blk(PS, 2);
    surf_ucontract_kernel<<<PB * (PS / 2), blk>>>(out);
}